// round 5
// baseline (speedup 1.0000x reference)
#include <cuda_runtime.h>
#include <math.h>
#include <stdint.h>

// ---------------------------------------------------------------------------
// TT feed-forward via dense weight materialization + tf32 mma.sync GEMMs.
// CTA tile 256x128, warp tile 64x64, 3-stage cp.async, ldmatrix fragments.
//   W1t[4096,1024], W2t[1024,4096]  (transposed, tf32-rounded)
//   Xr  = tf32(x);  H = tf32(GELU(Xr @ W1t^T + b1));  out = H @ W2t^T + b2
// ---------------------------------------------------------------------------

__device__ float g_P  [128 * 256 * 16];
__device__ float g_W1t[4096 * 1024];
__device__ float g_W2t[1024 * 4096];
__device__ float g_H  [4096 * 4096];
__device__ float g_Xr [4096 * 1024];

// ------------------------------ helpers -----------------------------------
__device__ __forceinline__ uint32_t smem_u32(const void* p) {
    uint32_t a;
    asm("{ .reg .u64 t; cvta.to.shared.u64 t, %1; cvt.u32.u64 %0, t; }"
        : "=r"(a) : "l"(p));
    return a;
}
__device__ __forceinline__ float to_tf32(float f) {
    uint32_t u;
    asm("cvt.rna.tf32.f32 %0, %1;" : "=r"(u) : "f"(f));
    return __uint_as_float(u);
}
__device__ __forceinline__ void cp16(uint32_t dst, const void* src) {
    asm volatile("cp.async.cg.shared.global [%0], [%1], 16;"
                 :: "r"(dst), "l"(src));
}
#define CP_COMMIT() asm volatile("cp.async.commit_group;")
#define CP_WAIT(n)  asm volatile("cp.async.wait_group %0;" :: "n"(n))

__device__ __forceinline__ void mma_tf32(float c[4], const uint32_t a[4],
                                         const uint32_t b[2]) {
    asm volatile(
        "mma.sync.aligned.m16n8k8.row.col.f32.tf32.tf32.f32 "
        "{%0,%1,%2,%3}, {%4,%5,%6,%7}, {%8,%9}, {%0,%1,%2,%3};"
        : "+f"(c[0]), "+f"(c[1]), "+f"(c[2]), "+f"(c[3])
        : "r"(a[0]), "r"(a[1]), "r"(a[2]), "r"(a[3]), "r"(b[0]), "r"(b[1]));
}
__device__ __forceinline__ void ldsm4(uint32_t& r0, uint32_t& r1,
                                      uint32_t& r2, uint32_t& r3,
                                      uint32_t addr) {
    asm volatile("ldmatrix.sync.aligned.m8n8.x4.shared.b16 {%0,%1,%2,%3}, [%4];"
                 : "=r"(r0), "=r"(r1), "=r"(r2), "=r"(r3) : "r"(addr));
}

// ------------------------- weight materialization -------------------------
// P[pair][j][r2] = sum_r1 c0[pair*16+r1] * c1[(r1*256+j)*16+r2]
// one thread -> 4 outputs (one float4 of r2), 131072 threads.
__global__ void pair_kernel(const float* __restrict__ c0,
                            const float* __restrict__ c1) {
    int idx  = blockIdx.x * blockDim.x + threadIdx.x;   // 131072
    int r2q  = idx & 3;
    int j    = (idx >> 2) & 255;
    int pair = idx >> 10;
    const float* c0p = c0 + pair * 16;
    float4 acc = make_float4(0, 0, 0, 0);
#pragma unroll
    for (int r1 = 0; r1 < 16; ++r1) {
        float w = c0p[r1];
        float4 v = ((const float4*)(c1 + (r1 * 256 + j) * 16))[r2q];
        acc.x += w * v.x; acc.y += w * v.y;
        acc.z += w * v.z; acc.w += w * v.w;
    }
    ((float4*)g_P)[idx] = acc;
}

// W1t[m, n]: m in [0,4096) hidden (16,16,16), n in [0,1024) embed (8,16,8)
__global__ void w1t_kernel(const float* __restrict__ c2) {
    __shared__ float s[16 * 16 * 8];   // [r2][m3][n3]
    for (int i = threadIdx.x; i < 2048; i += blockDim.x) {
        int r2 = i >> 7, n3 = (i >> 4) & 7, m3 = i & 15;   // c2: [r2][n3][m3]
        s[(r2 * 16 + m3) * 8 + n3] = c2[i];
    }
    __syncthreads();
    int idx = blockIdx.x * blockDim.x + threadIdx.x;    // 524288
    int nq = idx & 127;            // n1*16+n2
    int m  = idx >> 7;
    int n1 = nq >> 4, n2 = nq & 15;
    int m1 = m >> 8, m2 = (m >> 4) & 15, m3 = m & 15;
    const float4* p4 = (const float4*)(g_P +
        (((n1 * 16 + m1) * 256) + (n2 * 16 + m2)) * 16);
    float pv[16];
    *(float4*)&pv[0]  = p4[0]; *(float4*)&pv[4]  = p4[1];
    *(float4*)&pv[8]  = p4[2]; *(float4*)&pv[12] = p4[3];
    float acc[8] = {0, 0, 0, 0, 0, 0, 0, 0};
#pragma unroll
    for (int r2 = 0; r2 < 16; ++r2) {
        const float* sr = s + (r2 * 16 + m3) * 8;
#pragma unroll
        for (int j = 0; j < 8; ++j) acc[j] += pv[r2] * sr[j];
    }
    float4 o0, o1;
    o0.x = to_tf32(acc[0]); o0.y = to_tf32(acc[1]);
    o0.z = to_tf32(acc[2]); o0.w = to_tf32(acc[3]);
    o1.x = to_tf32(acc[4]); o1.y = to_tf32(acc[5]);
    o1.z = to_tf32(acc[6]); o1.w = to_tf32(acc[7]);
    float4* o = (float4*)(g_W1t + (size_t)m * 1024 + nq * 8);
    o[0] = o0; o[1] = o1;
}

// W2t[m, n]: m in [0,1024) embed (8,16,8), n in [0,4096) hidden (16,16,16)
__global__ void w2t_kernel(const float* __restrict__ c2) {
    __shared__ float s[16 * 8 * 16];   // [r2][m3][n3]
    for (int i = threadIdx.x; i < 2048; i += blockDim.x) {
        int r2 = i >> 7, n3 = (i >> 3) & 15, m3 = i & 7;   // c2: [r2][n3][m3]
        s[(r2 * 8 + m3) * 16 + n3] = c2[i];
    }
    __syncthreads();
    int idx = blockIdx.x * blockDim.x + threadIdx.x;    // 524288
    int nh = idx & 511;            // n >> 3
    int m  = idx >> 9;
    int n1 = nh >> 5, n2 = (nh >> 1) & 15, n3b = (nh & 1) * 8;
    int m1 = m >> 7, m2 = (m >> 3) & 15, m3 = m & 7;
    const float4* p4 = (const float4*)(g_P +
        (((n1 * 8 + m1) * 256) + (n2 * 16 + m2)) * 16);
    float pv[16];
    *(float4*)&pv[0]  = p4[0]; *(float4*)&pv[4]  = p4[1];
    *(float4*)&pv[8]  = p4[2]; *(float4*)&pv[12] = p4[3];
    float acc[8] = {0, 0, 0, 0, 0, 0, 0, 0};
#pragma unroll
    for (int r2 = 0; r2 < 16; ++r2) {
        const float* sr = s + (r2 * 8 + m3) * 16 + n3b;
#pragma unroll
        for (int j = 0; j < 8; ++j) acc[j] += pv[r2] * sr[j];
    }
    float4 o0, o1;
    o0.x = to_tf32(acc[0]); o0.y = to_tf32(acc[1]);
    o0.z = to_tf32(acc[2]); o0.w = to_tf32(acc[3]);
    o1.x = to_tf32(acc[4]); o1.y = to_tf32(acc[5]);
    o1.z = to_tf32(acc[6]); o1.w = to_tf32(acc[7]);
    float4* o = (float4*)(g_W2t + (size_t)m * 4096 + nh * 8);
    o[0] = o0; o[1] = o1;
}

__global__ void xround_kernel(const float4* __restrict__ x, float4* __restrict__ o) {
    int i = blockIdx.x * blockDim.x + threadIdx.x;
    float4 v = x[i];
    v.x = to_tf32(v.x); v.y = to_tf32(v.y);
    v.z = to_tf32(v.z); v.w = to_tf32(v.w);
    o[i] = v;
}

// ------------------------------- tf32 GEMM --------------------------------
// C[M,N] = A[M,K] * B[N,K]^T + bias.  fuse=1: C = tf32(gelu_exact(.)).
// CTA tile 256x128, BK=32, 8 warps (warp tile 64x64, 4m x 2n layout),
// 3-stage cp.async, SW128-swizzled smem, ldmatrix.x4 fragment loads.
#define STAGE_B 49152                     // A 32K + B 16K per stage

__global__ void __launch_bounds__(256, 1) gemm_tf32(
    const float* __restrict__ A, const float* __restrict__ B,
    const float* __restrict__ bias, float* __restrict__ C,
    int K, int N, int fuse) {
    extern __shared__ char smem[];
    uint32_t sb = smem_u32(smem);

    int tid  = threadIdx.x;
    int lane = tid & 31;
    int q    = lane & 3;
    int g8   = lane >> 2;
    int warp = tid >> 5;
    int wm   = (warp & 3) * 64;          // 4 m-warps
    int wn   = (warp >> 2) * 64;         // 2 n-warps

    size_t rowBase = (size_t)blockIdx.y * 256;
    size_t colBase = (size_t)blockIdx.x * 128;
    const float* Ag = A + rowBase * (size_t)K;
    const float* Bg = B + colBase * (size_t)K;

    // cp.async: A = 2048 16B-chunks (256 rows x 8), B = 1024 (128 rows x 8)
#define LOAD_STAGE(s, buf) do {                                              \
    uint32_t stg = sb + (uint32_t)(buf) * STAGE_B;                           \
    size_t koff = (size_t)(s) * 32;                                          \
    _Pragma("unroll")                                                        \
    for (int i = 0; i < 8; ++i) {                                            \
        int id = tid + 256 * i;                                              \
        int r = id >> 3, j = id & 7;                                         \
        uint32_t off = (uint32_t)(r * 128 + ((j ^ (r & 7)) << 4));           \
        cp16(stg + off, Ag + (size_t)r * K + koff + j * 4);                  \
    }                                                                        \
    _Pragma("unroll")                                                        \
    for (int i = 0; i < 4; ++i) {                                            \
        int id = tid + 256 * i;                                              \
        int r = id >> 3, j = id & 7;                                         \
        uint32_t off = (uint32_t)(r * 128 + ((j ^ (r & 7)) << 4));           \
        cp16(stg + 32768 + off, Bg + (size_t)r * K + koff + j * 4);          \
    }                                                                        \
    CP_COMMIT();                                                             \
} while (0)

    // ldmatrix per-lane geometry (identical to validated R4 layout)
    int rA = ((lane >> 3) & 1) * 8 + (lane & 7);   // A row-in-slab
    int cA = (lane >> 4) & 1;                      // A chunk half
    int rB = ((lane >> 4) & 1) * 8 + (lane & 7);   // B row-in-slab
    int cB = (lane >> 3) & 1;                      // B chunk half

    uint32_t aBase[4], aSwz[4], bBase[4], bSwz[4];
#pragma unroll
    for (int mt = 0; mt < 4; ++mt) {
        int row = wm + mt * 16 + rA;
        aBase[mt] = (uint32_t)(row * 128);
        aSwz[mt]  = (uint32_t)(row & 7);
    }
#pragma unroll
    for (int p = 0; p < 4; ++p) {
        int row = wn + p * 16 + rB;
        bBase[p] = (uint32_t)(32768 + row * 128);
        bSwz[p]  = (uint32_t)(row & 7);
    }

    float acc[4][8][4];
#pragma unroll
    for (int i = 0; i < 4; ++i)
#pragma unroll
        for (int j = 0; j < 8; ++j)
#pragma unroll
            for (int k = 0; k < 4; ++k) acc[i][j][k] = 0.f;

    int nS = K >> 5;
    LOAD_STAGE(0, 0);
    LOAD_STAGE(1, 1);

    int buf = 0;
    for (int s = 0; s < nS; ++s) {
        if (s + 2 < nS) CP_WAIT(1); else CP_WAIT(0);
        __syncthreads();
        if (s + 2 < nS) {
            int nb = buf - 1; if (nb < 0) nb += 3;
            LOAD_STAGE(s + 2, nb);
        }

        uint32_t stg = sb + (uint32_t)buf * STAGE_B;
#pragma unroll
        for (int ks = 0; ks < 4; ++ks) {
            uint32_t af[4][4], bf[8][2];
#pragma unroll
            for (int mt = 0; mt < 4; ++mt) {
                uint32_t ad = stg + aBase[mt] +
                              ((((uint32_t)(ks * 2) + cA) ^ aSwz[mt]) << 4);
                ldsm4(af[mt][0], af[mt][1], af[mt][2], af[mt][3], ad);
            }
#pragma unroll
            for (int p = 0; p < 4; ++p) {
                uint32_t bd = stg + bBase[p] +
                              ((((uint32_t)(ks * 2) + cB) ^ bSwz[p]) << 4);
                ldsm4(bf[2 * p][0], bf[2 * p][1],
                      bf[2 * p + 1][0], bf[2 * p + 1][1], bd);
            }
#pragma unroll
            for (int mt = 0; mt < 4; ++mt)
#pragma unroll
                for (int nt = 0; nt < 8; ++nt)
                    mma_tf32(acc[mt][nt], af[mt], bf[nt]);
        }
        buf = (buf == 2) ? 0 : buf + 1;
    }

    // ---- epilogue: bias (+ exact-erf GELU + tf32 round), float2 stores ----
#pragma unroll
    for (int nt = 0; nt < 8; ++nt) {
        int col = (int)colBase + wn + nt * 8 + 2 * q;
        float bx = bias[col], by = bias[col + 1];
#pragma unroll
        for (int mt = 0; mt < 4; ++mt) {
            size_t row0 = rowBase + wm + mt * 16 + g8;
            float v0 = acc[mt][nt][0] + bx;
            float v1 = acc[mt][nt][1] + by;
            float v2 = acc[mt][nt][2] + bx;
            float v3 = acc[mt][nt][3] + by;
            if (fuse) {
                v0 = to_tf32(0.5f * v0 * (1.0f + erff(v0 * 0.70710678118654752f)));
                v1 = to_tf32(0.5f * v1 * (1.0f + erff(v1 * 0.70710678118654752f)));
                v2 = to_tf32(0.5f * v2 * (1.0f + erff(v2 * 0.70710678118654752f)));
                v3 = to_tf32(0.5f * v3 * (1.0f + erff(v3 * 0.70710678118654752f)));
            }
            *(float2*)&C[row0 * (size_t)N + col]       = make_float2(v0, v1);
            *(float2*)&C[(row0 + 8) * (size_t)N + col] = make_float2(v2, v3);
        }
    }
#undef LOAD_STAGE
}

// --------------------------------- launch ---------------------------------
extern "C" void kernel_launch(void* const* d_in, const int* in_sizes, int n_in,
                              void* d_out, int out_size) {
    const float* x   = (const float*)d_in[0];
    const float* c10 = (const float*)d_in[1];
    const float* c11 = (const float*)d_in[2];
    const float* c12 = (const float*)d_in[3];
    const float* b1  = (const float*)d_in[4];
    const float* c20 = (const float*)d_in[5];
    const float* c21 = (const float*)d_in[6];
    const float* c22 = (const float*)d_in[7];
    const float* b2  = (const float*)d_in[8];
    float* out = (float*)d_out;

    float *pW1t, *pW2t, *pH, *pXr;
    cudaGetSymbolAddress((void**)&pW1t, g_W1t);
    cudaGetSymbolAddress((void**)&pW2t, g_W2t);
    cudaGetSymbolAddress((void**)&pH,   g_H);
    cudaGetSymbolAddress((void**)&pXr,  g_Xr);

    const int SMEM = 3 * STAGE_B;   // 147456
    cudaFuncSetAttribute(gemm_tf32, cudaFuncAttributeMaxDynamicSharedMemorySize,
                         SMEM);

    xround_kernel<<<4096, 256>>>((const float4*)x, (float4*)pXr);

    pair_kernel<<<512, 256>>>(c10, c11);
    w1t_kernel<<<2048, 256>>>(c12);
    pair_kernel<<<512, 256>>>(c20, c21);
    w2t_kernel<<<2048, 256>>>(c22);

    // GEMM1: H = tf32(GELU(Xr @ W1t^T + b1))   grid 32x16
    gemm_tf32<<<dim3(32, 16), 256, SMEM>>>(pXr, pW1t, b1, pH, 1024, 4096, 1);
    // GEMM2: out = H @ W2t^T + b2              grid 8x16
    gemm_tf32<<<dim3(8, 16), 256, SMEM>>>(pH, pW2t, b2, out, 4096, 1024, 0);
}

// round 6
// speedup vs baseline: 1.7094x; 1.7094x over previous
#include <cuda_runtime.h>
#include <cuda_fp16.h>
#include <math.h>
#include <stdint.h>

// ---------------------------------------------------------------------------
// TT feed-forward via dense weight materialization + fp16 mma.sync GEMMs
// (fp32 accumulate). CTA tile 128x128, warp 64x32, BK=64 halves, 3-stage
// cp.async, SW128 swizzle, ldmatrix.x4 fragments.
//   W1t[4096,1024], W2t[1024,4096] (transposed, fp16)
//   Xh = half(x);  H = half(GELU(Xh @ W1t^T + b1));  out = H @ W2t^T + b2
// ---------------------------------------------------------------------------

__device__ float  g_P  [128 * 256 * 16];
__device__ __half g_W1t[4096 * 1024];
__device__ __half g_W2t[1024 * 4096];
__device__ __half g_H  [4096 * 4096];
__device__ __half g_Xh [4096 * 1024];

// ------------------------------ helpers -----------------------------------
__device__ __forceinline__ uint32_t smem_u32(const void* p) {
    uint32_t a;
    asm("{ .reg .u64 t; cvta.to.shared.u64 t, %1; cvt.u32.u64 %0, t; }"
        : "=r"(a) : "l"(p));
    return a;
}
__device__ __forceinline__ void cp16(uint32_t dst, const void* src) {
    asm volatile("cp.async.cg.shared.global [%0], [%1], 16;"
                 :: "r"(dst), "l"(src));
}
#define CP_COMMIT() asm volatile("cp.async.commit_group;")
#define CP_WAIT(n)  asm volatile("cp.async.wait_group %0;" :: "n"(n))

__device__ __forceinline__ void mma_f16(float c[4], const uint32_t a[4],
                                        const uint32_t b[2]) {
    asm volatile(
        "mma.sync.aligned.m16n8k16.row.col.f32.f16.f16.f32 "
        "{%0,%1,%2,%3}, {%4,%5,%6,%7}, {%8,%9}, {%0,%1,%2,%3};"
        : "+f"(c[0]), "+f"(c[1]), "+f"(c[2]), "+f"(c[3])
        : "r"(a[0]), "r"(a[1]), "r"(a[2]), "r"(a[3]), "r"(b[0]), "r"(b[1]));
}
__device__ __forceinline__ void ldsm4(uint32_t& r0, uint32_t& r1,
                                      uint32_t& r2, uint32_t& r3,
                                      uint32_t addr) {
    asm volatile("ldmatrix.sync.aligned.m8n8.x4.shared.b16 {%0,%1,%2,%3}, [%4];"
                 : "=r"(r0), "=r"(r1), "=r"(r2), "=r"(r3) : "r"(addr));
}
__device__ __forceinline__ uint32_t pack2(float a, float b) {
    __half2 h = __floats2half2_rn(a, b);
    return *(uint32_t*)&h;
}

// ------------------------- weight materialization -------------------------
// P[pair][j][r2] = sum_r1 c0[pair*16+r1] * c1[(r1*256+j)*16+r2]
__global__ void pair_kernel(const float* __restrict__ c0,
                            const float* __restrict__ c1) {
    int idx  = blockIdx.x * blockDim.x + threadIdx.x;   // 131072
    int r2q  = idx & 3;
    int j    = (idx >> 2) & 255;
    int pair = idx >> 10;
    const float* c0p = c0 + pair * 16;
    float4 acc = make_float4(0, 0, 0, 0);
#pragma unroll
    for (int r1 = 0; r1 < 16; ++r1) {
        float w = c0p[r1];
        float4 v = ((const float4*)(c1 + (r1 * 256 + j) * 16))[r2q];
        acc.x += w * v.x; acc.y += w * v.y;
        acc.z += w * v.z; acc.w += w * v.w;
    }
    ((float4*)g_P)[idx] = acc;
}

// W1t[m, n]: m in [0,4096) hidden (16,16,16), n in [0,1024) embed (8,16,8)
__global__ void w1t_kernel(const float* __restrict__ c2) {
    __shared__ float s[16 * 16 * 8];   // [r2][m3][n3]
    for (int i = threadIdx.x; i < 2048; i += blockDim.x) {
        int r2 = i >> 7, n3 = (i >> 4) & 7, m3 = i & 15;   // c2: [r2][n3][m3]
        s[(r2 * 16 + m3) * 8 + n3] = c2[i];
    }
    __syncthreads();
    int idx = blockIdx.x * blockDim.x + threadIdx.x;    // 524288
    int nq = idx & 127;            // n1*16+n2
    int m  = idx >> 7;
    int n1 = nq >> 4, n2 = nq & 15;
    int m1 = m >> 8, m2 = (m >> 4) & 15, m3 = m & 15;
    const float4* p4 = (const float4*)(g_P +
        (((n1 * 16 + m1) * 256) + (n2 * 16 + m2)) * 16);
    float pv[16];
    *(float4*)&pv[0]  = p4[0]; *(float4*)&pv[4]  = p4[1];
    *(float4*)&pv[8]  = p4[2]; *(float4*)&pv[12] = p4[3];
    float acc[8] = {0, 0, 0, 0, 0, 0, 0, 0};
#pragma unroll
    for (int r2 = 0; r2 < 16; ++r2) {
        const float* sr = s + (r2 * 16 + m3) * 8;
#pragma unroll
        for (int j = 0; j < 8; ++j) acc[j] += pv[r2] * sr[j];
    }
    uint4 o;
    o.x = pack2(acc[0], acc[1]); o.y = pack2(acc[2], acc[3]);
    o.z = pack2(acc[4], acc[5]); o.w = pack2(acc[6], acc[7]);
    *(uint4*)(g_W1t + (size_t)m * 1024 + nq * 8) = o;
}

// W2t[m, n]: m in [0,1024) embed (8,16,8), n in [0,4096) hidden (16,16,16)
__global__ void w2t_kernel(const float* __restrict__ c2) {
    __shared__ float s[16 * 8 * 16];   // [r2][m3][n3]
    for (int i = threadIdx.x; i < 2048; i += blockDim.x) {
        int r2 = i >> 7, n3 = (i >> 3) & 15, m3 = i & 7;   // c2: [r2][n3][m3]
        s[(r2 * 8 + m3) * 16 + n3] = c2[i];
    }
    __syncthreads();
    int idx = blockIdx.x * blockDim.x + threadIdx.x;    // 524288
    int nh = idx & 511;            // n >> 3
    int m  = idx >> 9;
    int n1 = nh >> 5, n2 = (nh >> 1) & 15, n3b = (nh & 1) * 8;
    int m1 = m >> 7, m2 = (m >> 3) & 15, m3 = m & 7;
    const float4* p4 = (const float4*)(g_P +
        (((n1 * 8 + m1) * 256) + (n2 * 16 + m2)) * 16);
    float pv[16];
    *(float4*)&pv[0]  = p4[0]; *(float4*)&pv[4]  = p4[1];
    *(float4*)&pv[8]  = p4[2]; *(float4*)&pv[12] = p4[3];
    float acc[8] = {0, 0, 0, 0, 0, 0, 0, 0};
#pragma unroll
    for (int r2 = 0; r2 < 16; ++r2) {
        const float* sr = s + (r2 * 8 + m3) * 16 + n3b;
#pragma unroll
        for (int j = 0; j < 8; ++j) acc[j] += pv[r2] * sr[j];
    }
    uint4 o;
    o.x = pack2(acc[0], acc[1]); o.y = pack2(acc[2], acc[3]);
    o.z = pack2(acc[4], acc[5]); o.w = pack2(acc[6], acc[7]);
    *(uint4*)(g_W2t + (size_t)m * 4096 + nh * 8) = o;
}

// x -> half, 8 elements / thread
__global__ void xhalf_kernel(const float4* __restrict__ x, uint4* __restrict__ o) {
    int i = blockIdx.x * blockDim.x + threadIdx.x;      // 524288
    float4 v0 = x[2 * i], v1 = x[2 * i + 1];
    uint4 r;
    r.x = pack2(v0.x, v0.y); r.y = pack2(v0.z, v0.w);
    r.z = pack2(v1.x, v1.y); r.w = pack2(v1.z, v1.w);
    o[i] = r;
}

// ------------------------------- fp16 GEMM --------------------------------
// C[M,N] = A[M,K] * B[N,K]^T + bias.  fuse=1: C(half) = GELU(.), else C float.
// CTA 128x128, BK=64 halves (128B rows), 8 warps (64x32), 3-stage cp.async.
#define STAGE_B 32768                     // A 16K + B 16K per stage

__global__ void __launch_bounds__(256, 2) gemm_f16(
    const __half* __restrict__ A, const __half* __restrict__ B,
    const float* __restrict__ bias, void* __restrict__ Cv,
    int K, int N, int fuse) {
    extern __shared__ char smem[];
    uint32_t sb = smem_u32(smem);

    int tid  = threadIdx.x;
    int lane = tid & 31;
    int q    = lane & 3;
    int g8   = lane >> 2;
    int warp = tid >> 5;
    int wm   = (warp & 1) * 64;
    int wn   = (warp >> 1) * 32;

    size_t rowBase = (size_t)blockIdx.y * 128;
    size_t colBase = (size_t)blockIdx.x * 128;
    const __half* Ag = A + rowBase * (size_t)K;
    const __half* Bg = B + colBase * (size_t)K;

    // per stage: A 128 rows x 8 16B-chunks, B same. 8 cp16/thread.
#define LOAD_STAGE(s, buf) do {                                              \
    uint32_t stg = sb + (uint32_t)(buf) * STAGE_B;                           \
    size_t koff = (size_t)(s) * 64;                                          \
    _Pragma("unroll")                                                        \
    for (int i = 0; i < 4; ++i) {                                            \
        int id = tid + 256 * i;                                              \
        int r = id >> 3, j = id & 7;                                         \
        uint32_t off = (uint32_t)(r * 128 + ((j ^ (r & 7)) << 4));           \
        cp16(stg + off,         Ag + (size_t)r * K + koff + j * 8);          \
        cp16(stg + 16384 + off, Bg + (size_t)r * K + koff + j * 8);          \
    }                                                                        \
    CP_COMMIT();                                                             \
} while (0)

    // ldmatrix lane geometry (16x16 b16 tile: row = lane&15, 16B-half = lane>>4)
    int rT = lane & 15;
    int cT = lane >> 4;

    uint32_t aBase[4], aSwz[4], bBase[2], bSwz[2];
#pragma unroll
    for (int mt = 0; mt < 4; ++mt) {
        int row = wm + mt * 16 + rT;
        aBase[mt] = (uint32_t)(row * 128);
        aSwz[mt]  = (uint32_t)(row & 7);
    }
#pragma unroll
    for (int p = 0; p < 2; ++p) {
        int row = wn + p * 16 + rT;
        bBase[p] = (uint32_t)(16384 + row * 128);
        bSwz[p]  = (uint32_t)(row & 7);
    }

    float acc[4][4][4];
#pragma unroll
    for (int i = 0; i < 4; ++i)
#pragma unroll
        for (int j = 0; j < 4; ++j)
#pragma unroll
            for (int k = 0; k < 4; ++k) acc[i][j][k] = 0.f;

    int nS = K >> 6;
    LOAD_STAGE(0, 0);
    LOAD_STAGE(1, 1);

    int buf = 0;
    for (int s = 0; s < nS; ++s) {
        if (s + 2 < nS) CP_WAIT(1); else CP_WAIT(0);
        __syncthreads();
        if (s + 2 < nS) {
            int nb = buf - 1; if (nb < 0) nb += 3;
            LOAD_STAGE(s + 2, nb);
        }

        uint32_t stg = sb + (uint32_t)buf * STAGE_B;
#pragma unroll
        for (int ks = 0; ks < 4; ++ks) {           // k16 steps within 64-chunk
            uint32_t af[4][4], bf[4][2];
#pragma unroll
            for (int mt = 0; mt < 4; ++mt) {
                uint32_t ad = stg + aBase[mt] +
                              ((((uint32_t)(ks * 2) + cT) ^ aSwz[mt]) << 4);
                ldsm4(af[mt][0], af[mt][1], af[mt][2], af[mt][3], ad);
            }
#pragma unroll
            for (int p = 0; p < 2; ++p) {
                uint32_t bd = stg + bBase[p] +
                              ((((uint32_t)(ks * 2) + cT) ^ bSwz[p]) << 4);
                uint32_t r0, r1, r2, r3;
                ldsm4(r0, r1, r2, r3, bd);
                bf[2 * p][0] = r0; bf[2 * p][1] = r2;       // n tile p*16..+7
                bf[2 * p + 1][0] = r1; bf[2 * p + 1][1] = r3; // +8..+15
            }
#pragma unroll
            for (int mt = 0; mt < 4; ++mt)
#pragma unroll
                for (int nt = 0; nt < 4; ++nt)
                    mma_f16(acc[mt][nt], af[mt], bf[nt]);
        }
        buf = (buf == 2) ? 0 : buf + 1;
    }

    // ---- epilogue ----
#pragma unroll
    for (int nt = 0; nt < 4; ++nt) {
        int col = (int)colBase + wn + nt * 8 + 2 * q;
        float bx = bias[col], by = bias[col + 1];
#pragma unroll
        for (int mt = 0; mt < 4; ++mt) {
            size_t row0 = rowBase + wm + mt * 16 + g8;
            float v0 = acc[mt][nt][0] + bx;
            float v1 = acc[mt][nt][1] + by;
            float v2 = acc[mt][nt][2] + bx;
            float v3 = acc[mt][nt][3] + by;
            if (fuse) {
                v0 = 0.5f * v0 * (1.0f + erff(v0 * 0.70710678118654752f));
                v1 = 0.5f * v1 * (1.0f + erff(v1 * 0.70710678118654752f));
                v2 = 0.5f * v2 * (1.0f + erff(v2 * 0.70710678118654752f));
                v3 = 0.5f * v3 * (1.0f + erff(v3 * 0.70710678118654752f));
                __half* C = (__half*)Cv;
                *(uint32_t*)&C[row0 * (size_t)N + col]       = pack2(v0, v1);
                *(uint32_t*)&C[(row0 + 8) * (size_t)N + col] = pack2(v2, v3);
            } else {
                float* C = (float*)Cv;
                *(float2*)&C[row0 * (size_t)N + col]       = make_float2(v0, v1);
                *(float2*)&C[(row0 + 8) * (size_t)N + col] = make_float2(v2, v3);
            }
        }
    }
#undef LOAD_STAGE
}

// --------------------------------- launch ---------------------------------
extern "C" void kernel_launch(void* const* d_in, const int* in_sizes, int n_in,
                              void* d_out, int out_size) {
    const float* x   = (const float*)d_in[0];
    const float* c10 = (const float*)d_in[1];
    const float* c11 = (const float*)d_in[2];
    const float* c12 = (const float*)d_in[3];
    const float* b1  = (const float*)d_in[4];
    const float* c20 = (const float*)d_in[5];
    const float* c21 = (const float*)d_in[6];
    const float* c22 = (const float*)d_in[7];
    const float* b2  = (const float*)d_in[8];
    float* out = (float*)d_out;

    __half *pW1t, *pW2t, *pH, *pXh;
    cudaGetSymbolAddress((void**)&pW1t, g_W1t);
    cudaGetSymbolAddress((void**)&pW2t, g_W2t);
    cudaGetSymbolAddress((void**)&pH,   g_H);
    cudaGetSymbolAddress((void**)&pXh,  g_Xh);

    const int SMEM = 3 * STAGE_B;   // 98304
    cudaFuncSetAttribute(gemm_f16, cudaFuncAttributeMaxDynamicSharedMemorySize,
                         SMEM);

    xhalf_kernel<<<2048, 256>>>((const float4*)x, (uint4*)pXh);

    pair_kernel<<<512, 256>>>(c10, c11);
    w1t_kernel<<<2048, 256>>>(c12);
    pair_kernel<<<512, 256>>>(c20, c21);
    w2t_kernel<<<2048, 256>>>(c22);

    // GEMM1: H = half(GELU(Xh @ W1t^T + b1))   grid 32x32
    gemm_f16<<<dim3(32, 32), 256, SMEM>>>(pXh, pW1t, b1, pH, 1024, 4096, 1);
    // GEMM2: out = H @ W2t^T + b2              grid 8x32
    gemm_f16<<<dim3(8, 32), 256, SMEM>>>(pH, pW2t, b2, out, 4096, 1024, 0);
}